// round 5
// baseline (speedup 1.0000x reference)
#include <cuda_runtime.h>
#include <math.h>
#include <stdint.h>

// Problem constants
#define BB 2
#define SS 2048
#define DD 1024
#define HH 16
#define HD 64
#define MM (BB * SS)   // 4096

// Scratch
__device__ __align__(16) float    g_q[BB * HH * SS * HD];     // raw fp32 Q
__device__ __align__(16) uint32_t g_kh[BB * HH * SS * HD];    // K hi tf32
__device__ __align__(16) uint32_t g_kl[BB * HH * SS * HD];    // K lo tf32
__device__ __align__(16) uint32_t g_vt[BB * HH * SS * HD];    // V tf32
__device__ __align__(16) uint32_t g_ctx[BB * SS * DD];        // ctx tf32 bits
__device__ __align__(16) uint32_t g_tq[MM * DD];              // tf32 inputs
__device__ __align__(16) uint32_t g_tk[MM * DD];
__device__ __align__(16) uint32_t g_tv[MM * DD];
__device__ __align__(16) uint32_t g_wq[DD * DD];              // tf32 weights
__device__ __align__(16) uint32_t g_wk[DD * DD];
__device__ __align__(16) uint32_t g_wv[DD * DD];
__device__ __align__(16) uint32_t g_wo[DD * DD];

// ---------------------------------------------------------------------------
// helpers
// ---------------------------------------------------------------------------
__device__ __forceinline__ uint32_t f2tf32(float f) {
    uint32_t u;
    asm("cvt.rna.tf32.f32 %0, %1;" : "=r"(u) : "f"(f));
    return u;
}

__device__ __forceinline__ void mma_tf32(float (&d)[4], const uint32_t (&a)[4],
                                         const uint32_t (&b)[2]) {
    asm volatile(
        "mma.sync.aligned.m16n8k8.row.col.f32.tf32.tf32.f32 "
        "{%0,%1,%2,%3}, {%4,%5,%6,%7}, {%8,%9}, {%0,%1,%2,%3};\n"
        : "+f"(d[0]), "+f"(d[1]), "+f"(d[2]), "+f"(d[3])
        : "r"(a[0]), "r"(a[1]), "r"(a[2]), "r"(a[3]), "r"(b[0]), "r"(b[1]));
}

__device__ __forceinline__ void ldsm4(uint32_t& r0, uint32_t& r1,
                                      uint32_t& r2, uint32_t& r3, uint32_t addr) {
    asm volatile("ldmatrix.sync.aligned.m8n8.x4.shared.b16 {%0,%1,%2,%3}, [%4];\n"
                 : "=r"(r0), "=r"(r1), "=r"(r2), "=r"(r3) : "r"(addr));
}

__device__ __forceinline__ void cp_async16(void* sm, const void* g) {
    uint32_t a = (uint32_t)__cvta_generic_to_shared(sm);
    asm volatile("cp.async.cg.shared.global [%0], [%1], 16;\n" :: "r"(a), "l"(g));
}
__device__ __forceinline__ void cp_commit() {
    asm volatile("cp.async.commit_group;\n");
}

// ---------------------------------------------------------------------------
// Kernel 0: convert inputs + weights to tf32 bits (RNA). grid = (1024, 7)
// ---------------------------------------------------------------------------
__global__ __launch_bounds__(256)
void cvt_tf32_all(const float* __restrict__ q, const float* __restrict__ k,
                  const float* __restrict__ v,
                  const float* __restrict__ wq, const float* __restrict__ wk,
                  const float* __restrict__ wv, const float* __restrict__ wo) {
    const int y = blockIdx.y;
    const float* src;
    uint32_t* dst;
    int n4;
    switch (y) {
        case 0: src = q;  dst = g_tq; n4 = MM * DD / 4; break;
        case 1: src = k;  dst = g_tk; n4 = MM * DD / 4; break;
        case 2: src = v;  dst = g_tv; n4 = MM * DD / 4; break;
        case 3: src = wq; dst = g_wq; n4 = DD * DD / 4; break;
        case 4: src = wk; dst = g_wk; n4 = DD * DD / 4; break;
        case 5: src = wv; dst = g_wv; n4 = DD * DD / 4; break;
        default: src = wo; dst = g_wo; n4 = DD * DD / 4; break;
    }
    for (int i = blockIdx.x * blockDim.x + threadIdx.x; i < n4;
         i += gridDim.x * blockDim.x) {
        float4 f = ((const float4*)src)[i];
        uint4 u;
        u.x = f2tf32(f.x); u.y = f2tf32(f.y);
        u.z = f2tf32(f.z); u.w = f2tf32(f.w);
        ((uint4*)dst)[i] = u;
    }
}

// ---------------------------------------------------------------------------
// tf32 GEMM core: C[m,n] = sum_k X[m,k]*W[n,k]
// 128x128 block, BK=32, 256 threads, cp.async double-buffered, ldmatrix frags.
// ---------------------------------------------------------------------------
#define PAD 36
#define PJ_SMEM (4 * 128 * PAD * 4)

__device__ __forceinline__ void gemm_issue(uint32_t* As, uint32_t* Bs,
                                           const uint32_t* __restrict__ X,
                                           const uint32_t* __restrict__ W,
                                           int m0, int n0, int k0,
                                           int lr, int lj) {
#pragma unroll
    for (int r = 0; r < 4; r++) {
        cp_async16(&As[(lr + r * 32) * PAD + lj],
                   &X[(size_t)(m0 + lr + r * 32) * DD + k0 + lj]);
        cp_async16(&Bs[(lr + r * 32) * PAD + lj],
                   &W[(size_t)(n0 + lr + r * 32) * DD + k0 + lj]);
    }
    cp_commit();
}

__device__ __forceinline__ void gemm_tile(const uint32_t* __restrict__ X,
                                          const uint32_t* __restrict__ W,
                                          uint32_t* sm, int m0, int n0,
                                          float (&acc)[4][4][4]) {
    uint32_t* As0 = sm;
    uint32_t* As1 = sm + 128 * PAD;
    uint32_t* Bs0 = sm + 2 * 128 * PAD;
    uint32_t* Bs1 = sm + 3 * 128 * PAD;

    const int tid  = threadIdx.x;
    const int warp = tid >> 5;
    const int lane = tid & 31;
    const int wm = (warp & 1) * 64;
    const int wn = (warp >> 1) * 32;
    const int lr = tid >> 3;
    const int lj = (tid & 7) * 4;

    // ldmatrix per-lane row addressing
    const int sel = lane >> 3;
    const int l7  = lane & 7;
    const int a_row = (sel & 1) * 8 + l7;
    const int a_col = (sel >> 1) * 4;
    const int b_row = (sel >> 1) * 8 + l7;
    const int b_col = (sel & 1) * 4;

    const uint32_t sa = (uint32_t)__cvta_generic_to_shared(sm);
    uint32_t aAddr[2][4], bAddr[2][2];
#pragma unroll
    for (int s = 0; s < 2; s++) {
        const uint32_t ab = sa + (s ? 128 * PAD * 4 : 0);
        const uint32_t bb = sa + (2 + s) * 128 * PAD * 4;
#pragma unroll
        for (int mi = 0; mi < 4; mi++)
            aAddr[s][mi] = ab + ((wm + mi * 16 + a_row) * PAD + a_col) * 4;
#pragma unroll
        for (int nj = 0; nj < 2; nj++)
            bAddr[s][nj] = bb + ((wn + nj * 16 + b_row) * PAD + b_col) * 4;
    }

    gemm_issue(As0, Bs0, X, W, m0, n0, 0, lr, lj);
    gemm_issue(As1, Bs1, X, W, m0, n0, 32, lr, lj);

    int s = 0;
    for (int k0 = 0; k0 < DD; k0 += 32, s ^= 1) {
        if (k0 + 32 < DD) asm volatile("cp.async.wait_group 1;\n");
        else              asm volatile("cp.async.wait_group 0;\n");
        __syncthreads();

#pragma unroll
        for (int ks = 0; ks < 4; ks++) {
            const uint32_t ko = ks * 32;   // bytes
            uint32_t af[4][4], bf[4][2];
#pragma unroll
            for (int mi = 0; mi < 4; mi++)
                ldsm4(af[mi][0], af[mi][1], af[mi][2], af[mi][3],
                      aAddr[s][mi] + ko);
#pragma unroll
            for (int nj = 0; nj < 2; nj++)
                ldsm4(bf[nj * 2][0], bf[nj * 2][1], bf[nj * 2 + 1][0],
                      bf[nj * 2 + 1][1], bAddr[s][nj] + ko);
#pragma unroll
            for (int mi = 0; mi < 4; mi++)
#pragma unroll
                for (int ni = 0; ni < 4; ni++)
                    mma_tf32(acc[mi][ni], af[mi], bf[ni]);
        }
        __syncthreads();
        if (k0 + 64 < DD)
            gemm_issue(s ? As1 : As0, s ? Bs1 : Bs0, X, W, m0, n0, k0 + 64, lr, lj);
    }
}

// ---------------------------------------------------------------------------
// Kernel 1: QKV projection. grid = (8, 32, 3)
// Q -> raw fp32; K -> hi/lo tf32 planes; V -> tf32 bits. All [B,H,S,HD].
// ---------------------------------------------------------------------------
__global__ __launch_bounds__(256)
void qkv_proj_tc(const float* __restrict__ bq, const float* __restrict__ bk,
                 const float* __restrict__ bv) {
    extern __shared__ uint32_t gsm[];
    const int which = blockIdx.z;
    const uint32_t* __restrict__ X    = (which == 0) ? g_tq : (which == 1) ? g_tk : g_tv;
    const uint32_t* __restrict__ W    = (which == 0) ? g_wq : (which == 1) ? g_wk : g_wv;
    const float*    __restrict__ bias = (which == 0) ? bq   : (which == 1) ? bk   : bv;

    float acc[4][4][4];
#pragma unroll
    for (int mi = 0; mi < 4; mi++)
#pragma unroll
        for (int ni = 0; ni < 4; ni++)
#pragma unroll
            for (int r = 0; r < 4; r++) acc[mi][ni][r] = 0.f;

    const int m0 = blockIdx.y * 128;
    const int n0 = blockIdx.x * 128;
    gemm_tile(X, W, gsm, m0, n0, acc);

    const int tid  = threadIdx.x;
    const int warp = tid >> 5;
    const int lane = tid & 31;
    const int g = lane >> 2, t = lane & 3;
    const int wm = (warp & 1) * 64;
    const int wn = (warp >> 1) * 32;

#pragma unroll
    for (int mi = 0; mi < 4; mi++) {
#pragma unroll
        for (int rr = 0; rr < 2; rr++) {
            const int m = m0 + wm + mi * 16 + rr * 8 + g;
            const int b = m >> 11;
            const int s = m & 2047;
#pragma unroll
            for (int ni = 0; ni < 4; ni++) {
                const int n = n0 + wn + ni * 8 + t * 2;
                const int h = n >> 6;
                const int d = n & 63;
                const size_t off = ((size_t)(b * HH + h) * SS + s) * HD + d;
                float v0 = acc[mi][ni][rr * 2 + 0] + bias[n];
                float v1 = acc[mi][ni][rr * 2 + 1] + bias[n + 1];
                if (which == 0) {
                    float2 v; v.x = v0; v.y = v1;
                    *(float2*)&g_q[off] = v;
                } else if (which == 1) {
                    uint2 hi, lo;
                    hi.x = f2tf32(v0); lo.x = f2tf32(v0 - __uint_as_float(hi.x));
                    hi.y = f2tf32(v1); lo.y = f2tf32(v1 - __uint_as_float(hi.y));
                    *(uint2*)&g_kh[off] = hi;
                    *(uint2*)&g_kl[off] = lo;
                } else {
                    uint2 v; v.x = f2tf32(v0); v.y = f2tf32(v1);
                    *(uint2*)&g_vt[off] = v;
                }
            }
        }
    }
}

// ---------------------------------------------------------------------------
// Kernel 3: output projection. X = g_ctx (tf32 bits). grid = (8, 32)
// ---------------------------------------------------------------------------
__global__ __launch_bounds__(256)
void out_proj_tc(const float* __restrict__ bo, float* __restrict__ out) {
    extern __shared__ uint32_t gsm[];
    float acc[4][4][4];
#pragma unroll
    for (int mi = 0; mi < 4; mi++)
#pragma unroll
        for (int ni = 0; ni < 4; ni++)
#pragma unroll
            for (int r = 0; r < 4; r++) acc[mi][ni][r] = 0.f;

    const int m0 = blockIdx.y * 128;
    const int n0 = blockIdx.x * 128;
    gemm_tile(g_ctx, g_wo, gsm, m0, n0, acc);

    const int tid  = threadIdx.x;
    const int warp = tid >> 5;
    const int lane = tid & 31;
    const int g = lane >> 2, t = lane & 3;
    const int wm = (warp & 1) * 64;
    const int wn = (warp >> 1) * 32;

#pragma unroll
    for (int mi = 0; mi < 4; mi++) {
#pragma unroll
        for (int rr = 0; rr < 2; rr++) {
            const int m = m0 + wm + mi * 16 + rr * 8 + g;
#pragma unroll
            for (int ni = 0; ni < 4; ni++) {
                const int n = n0 + wn + ni * 8 + t * 2;
                float2 v;
                v.x = acc[mi][ni][rr * 2 + 0] + bo[n];
                v.y = acc[mi][ni][rr * 2 + 1] + bo[n + 1];
                *(float2*)&out[(size_t)m * DD + n] = v;
            }
        }
    }
}

// ---------------------------------------------------------------------------
// Kernel 2: tensor-core causal flash attention.
// CTA = 128 q-rows x (head, batch), 8 warps x m16, KV tiles of 64.
// Q hi-frags in registers (split once); Q-lo in-place in Qs; K pre-split
// hi/lo planes in gmem; V pre-tf32 in gmem. All frag loads via ldmatrix.
// Ps aliases Khi||Klo.
// ---------------------------------------------------------------------------
#define QP 68
#define FA_QS 0
#define FA_KHI (128 * QP)            // 8704
#define FA_KLO (FA_KHI + 64 * QP)    // + 4352
#define FA_VT  (FA_KLO + 64 * QP)    // + 4352
#define FA_WORDS (FA_VT + 64 * QP)   // 21760 words
#define FA_SMEM (FA_WORDS * 4)       // 87040 B

__global__ __launch_bounds__(256, 2)
void flash_attn_tc() {
    extern __shared__ float smem[];
    float*    Qs  = smem + FA_QS;                 // [128][QP] raw fp32 -> lo bits
    uint32_t* Khi = (uint32_t*)(smem + FA_KHI);   // [64][QP]
    uint32_t* Klo = (uint32_t*)(smem + FA_KLO);   // [64][QP]
    uint32_t* Vt  = (uint32_t*)(smem + FA_VT);    // [64][QP]
    uint32_t* Ps  = Khi;                          // alias [128][QP]

    const int qt = (gridDim.x - 1) - blockIdx.x;  // heavy tiles first
    const int h  = blockIdx.y;
    const int b  = blockIdx.z;
    const int tid  = threadIdx.x;
    const int warp = tid >> 5;
    const int lane = tid & 31;
    const int g = lane >> 2;
    const int t = lane & 3;
    const int wm = warp * 16;
    const int q0 = qt * 128;

    const float*    __restrict__ Qb = g_q  + (size_t)(b * HH + h) * SS * HD;
    const uint32_t* __restrict__ Hb = g_kh + (size_t)(b * HH + h) * SS * HD;
    const uint32_t* __restrict__ Lb = g_kl + (size_t)(b * HH + h) * SS * HD;
    const uint32_t* __restrict__ Vb = g_vt + (size_t)(b * HH + h) * SS * HD;

    // ldmatrix addressing
    const int sel = lane >> 3;
    const int l7  = lane & 7;
    const int a_row = (sel & 1) * 8 + l7;
    const int a_col = (sel >> 1) * 4;
    const int b_row = (sel >> 1) * 8 + l7;
    const int b_col = (sel & 1) * 4;

    const uint32_t qAddr = (uint32_t)__cvta_generic_to_shared(Qs) +
                           ((wm + a_row) * QP + a_col) * 4;
    const uint32_t pAddr = (uint32_t)__cvta_generic_to_shared(Ps) +
                           ((wm + a_row) * QP + a_col) * 4;
    uint32_t hAddr[4], lAddr[4];
#pragma unroll
    for (int p = 0; p < 4; p++) {
        hAddr[p] = (uint32_t)__cvta_generic_to_shared(Khi) +
                   ((p * 16 + b_row) * QP + b_col) * 4;
        lAddr[p] = (uint32_t)__cvta_generic_to_shared(Klo) +
                   ((p * 16 + b_row) * QP + b_col) * 4;
    }

    // stage raw Q tile (cp.async): 128 rows x 16 uint4
    {
        const int lr = tid >> 1;
        const int lc = (tid & 1) * 32;           // words
#pragma unroll
        for (int c = 0; c < 8; c++)
            cp_async16(&Qs[lr * QP + lc + c * 4],
                       &Qb[(size_t)(q0 + lr) * HD + lc + c * 4]);
        cp_commit();
        asm volatile("cp.async.wait_group 0;\n");
    }
    __syncthreads();

    // split Q: hi -> registers, lo -> in place (each slot owned by one thread)
    uint32_t ahi[8][4];
#pragma unroll
    for (int ks = 0; ks < 8; ks++) {
        const int kb = ks * 8;
        float r[4];
        r[0] = Qs[(wm + g)     * QP + kb + t];
        r[1] = Qs[(wm + g + 8) * QP + kb + t];
        r[2] = Qs[(wm + g)     * QP + kb + t + 4];
        r[3] = Qs[(wm + g + 8) * QP + kb + t + 4];
#pragma unroll
        for (int i = 0; i < 4; i++)
            ahi[ks][i] = f2tf32(r[i]);
        ((uint32_t*)Qs)[(wm + g)     * QP + kb + t]     = f2tf32(r[0] - __uint_as_float(ahi[ks][0]));
        ((uint32_t*)Qs)[(wm + g + 8) * QP + kb + t]     = f2tf32(r[1] - __uint_as_float(ahi[ks][1]));
        ((uint32_t*)Qs)[(wm + g)     * QP + kb + t + 4] = f2tf32(r[2] - __uint_as_float(ahi[ks][2]));
        ((uint32_t*)Qs)[(wm + g + 8) * QP + kb + t + 4] = f2tf32(r[3] - __uint_as_float(ahi[ks][3]));
    }
    __syncwarp();

    float oacc[8][4];
#pragma unroll
    for (int ni = 0; ni < 8; ni++)
#pragma unroll
        for (int r = 0; r < 4; r++) oacc[ni][r] = 0.f;
    float m0r = -1e30f, m1r = -1e30f, l0r = 0.f, l1r = 0.f;

    const float scale = 0.125f;
    const int ntiles = 2 * qt + 2;

    const int krow = tid >> 2;                   // 0..63
    const int kc   = (tid & 3) * 16;             // word offset

    for (int tt = 0; tt < ntiles; tt++) {
        const int k0 = tt * 64;
        // load Khi/Klo/Vt tiles (pure copies, no cvt)
#pragma unroll
        for (int c = 0; c < 4; c++) {
            cp_async16(&Khi[krow * QP + kc + c * 4],
                       &Hb[(size_t)(k0 + krow) * HD + kc + c * 4]);
            cp_async16(&Klo[krow * QP + kc + c * 4],
                       &Lb[(size_t)(k0 + krow) * HD + kc + c * 4]);
            cp_async16(&Vt[krow * QP + kc + c * 4],
                       &Vb[(size_t)(k0 + krow) * HD + kc + c * 4]);
        }
        cp_commit();
        asm volatile("cp.async.wait_group 0;\n");
        __syncthreads();

        // S = Q K^T via split-tf32 (3 MMAs), all frags via ldmatrix
        float sacc[8][4];
#pragma unroll
        for (int ni = 0; ni < 8; ni++)
#pragma unroll
            for (int r = 0; r < 4; r++) sacc[ni][r] = 0.f;

#pragma unroll
        for (int ks = 0; ks < 8; ks++) {
            const uint32_t ko = ks * 32;   // bytes
            uint32_t alo[4];
            ldsm4(alo[0], alo[1], alo[2], alo[3], qAddr + ko);
#pragma unroll
            for (int p = 0; p < 4; p++) {
                uint32_t h0, h1, h2, h3, lo0, lo1, lo2, lo3;
                ldsm4(h0, h1, h2, h3, hAddr[p] + ko);
                ldsm4(lo0, lo1, lo2, lo3, lAddr[p] + ko);
                {
                    uint32_t bh[2] = { h0, h1 }, bl[2] = { lo0, lo1 };
                    mma_tf32(sacc[2 * p], ahi[ks], bh);
                    mma_tf32(sacc[2 * p], ahi[ks], bl);
                    mma_tf32(sacc[2 * p], alo, bh);
                }
                {
                    uint32_t bh[2] = { h2, h3 }, bl[2] = { lo2, lo3 };
                    mma_tf32(sacc[2 * p + 1], ahi[ks], bh);
                    mma_tf32(sacc[2 * p + 1], ahi[ks], bl);
                    mma_tf32(sacc[2 * p + 1], alo, bh);
                }
            }
        }
        __syncthreads();   // Khi/Klo dead before Ps overwrites them

        // scale + causal mask (only last 2 tiles touch the diagonal)
        const bool need_mask = (tt >= ntiles - 2);
        const int qi0 = q0 + wm + g;
        const int qi1 = qi0 + 8;
#pragma unroll
        for (int ni = 0; ni < 8; ni++) {
            const int c0 = k0 + ni * 8 + 2 * t;
            sacc[ni][0] *= scale; sacc[ni][1] *= scale;
            sacc[ni][2] *= scale; sacc[ni][3] *= scale;
            if (need_mask) {
                if (c0 > qi0)     sacc[ni][0] -= 1e9f;
                if (c0 + 1 > qi0) sacc[ni][1] -= 1e9f;
                if (c0 > qi1)     sacc[ni][2] -= 1e9f;
                if (c0 + 1 > qi1) sacc[ni][3] -= 1e9f;
            }
        }

        // online softmax
        float mx0 = -1e30f, mx1 = -1e30f;
#pragma unroll
        for (int ni = 0; ni < 8; ni++) {
            mx0 = fmaxf(mx0, fmaxf(sacc[ni][0], sacc[ni][1]));
            mx1 = fmaxf(mx1, fmaxf(sacc[ni][2], sacc[ni][3]));
        }
        mx0 = fmaxf(mx0, __shfl_xor_sync(0xffffffffu, mx0, 1));
        mx0 = fmaxf(mx0, __shfl_xor_sync(0xffffffffu, mx0, 2));
        mx1 = fmaxf(mx1, __shfl_xor_sync(0xffffffffu, mx1, 1));
        mx1 = fmaxf(mx1, __shfl_xor_sync(0xffffffffu, mx1, 2));

        const float mn0 = fmaxf(m0r, mx0);
        const float mn1 = fmaxf(m1r, mx1);
        const float al0 = __expf(m0r - mn0);
        const float al1 = __expf(m1r - mn1);
        float s0 = 0.f, s1 = 0.f;
#pragma unroll
        for (int ni = 0; ni < 8; ni++) {
            float p0 = __expf(sacc[ni][0] - mn0);
            float p1 = __expf(sacc[ni][1] - mn0);
            float p2 = __expf(sacc[ni][2] - mn1);
            float p3 = __expf(sacc[ni][3] - mn1);
            s0 += p0 + p1; s1 += p2 + p3;
            uint32_t* pr0 = &Ps[(wm + g)     * QP + ni * 8 + 2 * t];
            uint32_t* pr1 = &Ps[(wm + g + 8) * QP + ni * 8 + 2 * t];
            pr0[0] = f2tf32(p0); pr0[1] = f2tf32(p1);
            pr1[0] = f2tf32(p2); pr1[1] = f2tf32(p3);
        }
        s0 += __shfl_xor_sync(0xffffffffu, s0, 1);
        s0 += __shfl_xor_sync(0xffffffffu, s0, 2);
        s1 += __shfl_xor_sync(0xffffffffu, s1, 1);
        s1 += __shfl_xor_sync(0xffffffffu, s1, 2);
        l0r = l0r * al0 + s0;
        l1r = l1r * al1 + s1;
        m0r = mn0; m1r = mn1;
#pragma unroll
        for (int ni = 0; ni < 8; ni++) {
            oacc[ni][0] *= al0; oacc[ni][1] *= al0;
            oacc[ni][2] *= al1; oacc[ni][3] *= al1;
        }
        __syncwarp();   // Ps rows are per-warp: write->read within warp

        // O += P @ V
#pragma unroll
        for (int ks = 0; ks < 8; ks++) {
            const int kb = ks * 8;
            uint32_t a[4];
            ldsm4(a[0], a[1], a[2], a[3], pAddr + ks * 32);
#pragma unroll
            for (int ni = 0; ni < 8; ni++) {
                uint32_t bf[2];
                bf[0] = Vt[(kb + t)     * QP + ni * 8 + g];
                bf[1] = Vt[(kb + t + 4) * QP + ni * 8 + g];
                mma_tf32(oacc[ni], a, bf);
            }
        }
        __syncthreads();   // Ps/Vt dead before next tile load
    }

    // normalize + store ctx as tf32 bits in [B,S,D]
    const float inv0 = 1.0f / l0r;
    const float inv1 = 1.0f / l1r;
    const int r0 = q0 + wm + g;
    uint32_t* out0 = g_ctx + ((size_t)(b * SS + r0))     * DD + h * HD;
    uint32_t* out1 = g_ctx + ((size_t)(b * SS + r0 + 8)) * DD + h * HD;
#pragma unroll
    for (int ni = 0; ni < 8; ni++) {
        const int c = ni * 8 + 2 * t;
        uint2 v0, v1;
        v0.x = f2tf32(oacc[ni][0] * inv0); v0.y = f2tf32(oacc[ni][1] * inv0);
        v1.x = f2tf32(oacc[ni][2] * inv1); v1.y = f2tf32(oacc[ni][3] * inv1);
        *(uint2*)&out0[c] = v0;
        *(uint2*)&out1[c] = v1;
    }
}

// ---------------------------------------------------------------------------
extern "C" void kernel_launch(void* const* d_in, const int* in_sizes, int n_in,
                              void* d_out, int out_size) {
    const float* query = (const float*)d_in[0];
    const float* key   = (const float*)d_in[1];
    const float* value = (const float*)d_in[2];
    // d_in[3] = mask (causal; applied analytically in-kernel)
    const float* Wq = (const float*)d_in[4];
    const float* bq = (const float*)d_in[5];
    const float* Wk = (const float*)d_in[6];
    const float* bk = (const float*)d_in[7];
    const float* Wv = (const float*)d_in[8];
    const float* bv = (const float*)d_in[9];
    const float* Wo = (const float*)d_in[10];
    const float* bo = (const float*)d_in[11];
    float* out = (float*)d_out;

    cudaFuncSetAttribute(flash_attn_tc,
                         cudaFuncAttributeMaxDynamicSharedMemorySize, FA_SMEM);
    cudaFuncSetAttribute(qkv_proj_tc,
                         cudaFuncAttributeMaxDynamicSharedMemorySize, PJ_SMEM);
    cudaFuncSetAttribute(out_proj_tc,
                         cudaFuncAttributeMaxDynamicSharedMemorySize, PJ_SMEM);

    dim3 gcvt(1024, 7);
    cvt_tf32_all<<<gcvt, 256>>>(query, key, value, Wq, Wk, Wv, Wo);

    dim3 gproj(DD / 128, MM / 128, 3);
    qkv_proj_tc<<<gproj, 256, PJ_SMEM>>>(bq, bk, bv);

    dim3 gfa(SS / 128, HH, BB);
    flash_attn_tc<<<gfa, 256, FA_SMEM>>>();

    dim3 gout(DD / 128, MM / 128);
    out_proj_tc<<<gout, 256, PJ_SMEM>>>(bo, out);
}

// round 7
// speedup vs baseline: 1.1029x; 1.1029x over previous
#include <cuda_runtime.h>
#include <math.h>
#include <stdint.h>

// Problem constants
#define BB 2
#define SS 2048
#define DD 1024
#define HH 16
#define HD 64
#define MM (BB * SS)   // 4096

// Scratch
__device__ __align__(16) float    g_q[BB * HH * SS * HD];     // raw fp32 Q
__device__ __align__(16) uint32_t g_kh[BB * HH * SS * HD];    // K hi tf32
__device__ __align__(16) uint32_t g_kl[BB * HH * SS * HD];    // K lo tf32
__device__ __align__(16) uint32_t g_vt[BB * HH * SS * HD];    // V tf32
__device__ __align__(16) uint32_t g_ctx[BB * SS * DD];        // ctx tf32 bits
__device__ __align__(16) uint32_t g_tq[MM * DD];              // tf32 inputs
__device__ __align__(16) uint32_t g_tk[MM * DD];
__device__ __align__(16) uint32_t g_tv[MM * DD];
__device__ __align__(16) uint32_t g_wq[DD * DD];              // tf32 weights
__device__ __align__(16) uint32_t g_wk[DD * DD];
__device__ __align__(16) uint32_t g_wv[DD * DD];
__device__ __align__(16) uint32_t g_wo[DD * DD];

// ---------------------------------------------------------------------------
// helpers
// ---------------------------------------------------------------------------
__device__ __forceinline__ uint32_t f2tf32(float f) {
    uint32_t u;
    asm("cvt.rna.tf32.f32 %0, %1;" : "=r"(u) : "f"(f));
    return u;
}

__device__ __forceinline__ void mma_tf32(float (&d)[4], const uint32_t (&a)[4],
                                         const uint32_t (&b)[2]) {
    asm volatile(
        "mma.sync.aligned.m16n8k8.row.col.f32.tf32.tf32.f32 "
        "{%0,%1,%2,%3}, {%4,%5,%6,%7}, {%8,%9}, {%0,%1,%2,%3};\n"
        : "+f"(d[0]), "+f"(d[1]), "+f"(d[2]), "+f"(d[3])
        : "r"(a[0]), "r"(a[1]), "r"(a[2]), "r"(a[3]), "r"(b[0]), "r"(b[1]));
}

__device__ __forceinline__ void ldsm4(uint32_t& r0, uint32_t& r1,
                                      uint32_t& r2, uint32_t& r3, uint32_t addr) {
    asm volatile("ldmatrix.sync.aligned.m8n8.x4.shared.b16 {%0,%1,%2,%3}, [%4];\n"
                 : "=r"(r0), "=r"(r1), "=r"(r2), "=r"(r3) : "r"(addr));
}

__device__ __forceinline__ void cp_async16(void* sm, const void* g) {
    uint32_t a = (uint32_t)__cvta_generic_to_shared(sm);
    asm volatile("cp.async.cg.shared.global [%0], [%1], 16;\n" :: "r"(a), "l"(g));
}
__device__ __forceinline__ void cp_commit() {
    asm volatile("cp.async.commit_group;\n");
}

// ---------------------------------------------------------------------------
// Kernel 0: convert inputs + weights to tf32 bits (RNA). grid = (1024, 7)
// ---------------------------------------------------------------------------
__global__ __launch_bounds__(256)
void cvt_tf32_all(const float* __restrict__ q, const float* __restrict__ k,
                  const float* __restrict__ v,
                  const float* __restrict__ wq, const float* __restrict__ wk,
                  const float* __restrict__ wv, const float* __restrict__ wo) {
    const int y = blockIdx.y;
    const float* src;
    uint32_t* dst;
    int n4;
    switch (y) {
        case 0: src = q;  dst = g_tq; n4 = MM * DD / 4; break;
        case 1: src = k;  dst = g_tk; n4 = MM * DD / 4; break;
        case 2: src = v;  dst = g_tv; n4 = MM * DD / 4; break;
        case 3: src = wq; dst = g_wq; n4 = DD * DD / 4; break;
        case 4: src = wk; dst = g_wk; n4 = DD * DD / 4; break;
        case 5: src = wv; dst = g_wv; n4 = DD * DD / 4; break;
        default: src = wo; dst = g_wo; n4 = DD * DD / 4; break;
    }
    for (int i = blockIdx.x * blockDim.x + threadIdx.x; i < n4;
         i += gridDim.x * blockDim.x) {
        float4 f = ((const float4*)src)[i];
        uint4 u;
        u.x = f2tf32(f.x); u.y = f2tf32(f.y);
        u.z = f2tf32(f.z); u.w = f2tf32(f.w);
        ((uint4*)dst)[i] = u;
    }
}

// ---------------------------------------------------------------------------
// tf32 GEMM core: C[m,n] = sum_k X[m,k]*W[n,k]
// Block tile 64x128, BK=32, 128 threads (4 warps, each 32x64), 2-stage
// cp.async, ldmatrix fragments, 4 CTAs/SM.
// ---------------------------------------------------------------------------
#define PAD 36
#define PJA (64 * PAD)
#define PJB (128 * PAD)
#define PJ_SMEM ((2 * PJA + 2 * PJB) * 4)   // 55296 B

__device__ __forceinline__ void gemm_issue(uint32_t* As, uint32_t* Bs,
                                           const uint32_t* __restrict__ X,
                                           const uint32_t* __restrict__ W,
                                           int m0, int n0, int k0, int tid) {
#pragma unroll
    for (int r = 0; r < 4; r++) {
        const int idx = tid + r * 128;
        const int row = idx >> 3;
        const int col = (idx & 7) * 4;
        cp_async16(&As[row * PAD + col], &X[(size_t)(m0 + row) * DD + k0 + col]);
    }
#pragma unroll
    for (int r = 0; r < 8; r++) {
        const int idx = tid + r * 128;
        const int row = idx >> 3;
        const int col = (idx & 7) * 4;
        cp_async16(&Bs[row * PAD + col], &W[(size_t)(n0 + row) * DD + k0 + col]);
    }
    cp_commit();
}

__device__ __forceinline__ void gemm_tile(const uint32_t* __restrict__ X,
                                          const uint32_t* __restrict__ W,
                                          uint32_t* sm, int m0, int n0,
                                          float (&acc)[2][8][4]) {
    uint32_t* As0 = sm;
    uint32_t* As1 = sm + PJA;
    uint32_t* Bs0 = sm + 2 * PJA;
    uint32_t* Bs1 = sm + 2 * PJA + PJB;

    const int tid  = threadIdx.x;
    const int warp = tid >> 5;
    const int lane = tid & 31;
    const int wm = (warp & 1) * 32;
    const int wn = (warp >> 1) * 64;

    const int sel = lane >> 3;
    const int l7  = lane & 7;
    const int a_row = (sel & 1) * 8 + l7;
    const int a_col = (sel >> 1) * 4;
    const int b_row = (sel >> 1) * 8 + l7;
    const int b_col = (sel & 1) * 4;

    const uint32_t sa = (uint32_t)__cvta_generic_to_shared(sm);
    uint32_t aAddr[2][2], bAddr[2][4];
#pragma unroll
    for (int s = 0; s < 2; s++) {
        const uint32_t ab = sa + (s ? PJA * 4 : 0);
        const uint32_t bb = sa + (2 * PJA + (s ? PJB : 0)) * 4;
#pragma unroll
        for (int mi = 0; mi < 2; mi++)
            aAddr[s][mi] = ab + ((wm + mi * 16 + a_row) * PAD + a_col) * 4;
#pragma unroll
        for (int nj = 0; nj < 4; nj++)
            bAddr[s][nj] = bb + ((wn + nj * 16 + b_row) * PAD + b_col) * 4;
    }

    gemm_issue(As0, Bs0, X, W, m0, n0, 0, tid);
    gemm_issue(As1, Bs1, X, W, m0, n0, 32, tid);

    int s = 0;
    for (int k0 = 0; k0 < DD; k0 += 32, s ^= 1) {
        if (k0 + 32 < DD) asm volatile("cp.async.wait_group 1;\n");
        else              asm volatile("cp.async.wait_group 0;\n");
        __syncthreads();

#pragma unroll
        for (int ks = 0; ks < 4; ks++) {
            const uint32_t ko = ks * 32;   // bytes
            uint32_t af[2][4], bf[8][2];
#pragma unroll
            for (int mi = 0; mi < 2; mi++)
                ldsm4(af[mi][0], af[mi][1], af[mi][2], af[mi][3],
                      aAddr[s][mi] + ko);
#pragma unroll
            for (int nj = 0; nj < 4; nj++)
                ldsm4(bf[nj * 2][0], bf[nj * 2][1], bf[nj * 2 + 1][0],
                      bf[nj * 2 + 1][1], bAddr[s][nj] + ko);
#pragma unroll
            for (int mi = 0; mi < 2; mi++)
#pragma unroll
                for (int ni = 0; ni < 8; ni++)
                    mma_tf32(acc[mi][ni], af[mi], bf[ni]);
        }
        __syncthreads();
        if (k0 + 64 < DD)
            gemm_issue(s ? As1 : As0, s ? Bs1 : Bs0, X, W, m0, n0, k0 + 64, tid);
    }
}

// ---------------------------------------------------------------------------
// Kernel 1: QKV projection. grid = (8, 64, 3), 128 threads.
// Q -> raw fp32; K -> hi/lo tf32 planes; V -> tf32 bits. All [B,H,S,HD].
// ---------------------------------------------------------------------------
__global__ __launch_bounds__(128, 4)
void qkv_proj_tc(const float* __restrict__ bq, const float* __restrict__ bk,
                 const float* __restrict__ bv) {
    extern __shared__ uint32_t gsm[];
    const int which = blockIdx.z;
    const uint32_t* __restrict__ X    = (which == 0) ? g_tq : (which == 1) ? g_tk : g_tv;
    const uint32_t* __restrict__ W    = (which == 0) ? g_wq : (which == 1) ? g_wk : g_wv;
    const float*    __restrict__ bias = (which == 0) ? bq   : (which == 1) ? bk   : bv;

    float acc[2][8][4];
#pragma unroll
    for (int mi = 0; mi < 2; mi++)
#pragma unroll
        for (int ni = 0; ni < 8; ni++)
#pragma unroll
            for (int r = 0; r < 4; r++) acc[mi][ni][r] = 0.f;

    const int m0 = blockIdx.y * 64;
    const int n0 = blockIdx.x * 128;
    gemm_tile(X, W, gsm, m0, n0, acc);

    const int tid  = threadIdx.x;
    const int warp = tid >> 5;
    const int lane = tid & 31;
    const int g = lane >> 2, t = lane & 3;
    const int wm = (warp & 1) * 32;
    const int wn = (warp >> 1) * 64;

#pragma unroll
    for (int mi = 0; mi < 2; mi++) {
#pragma unroll
        for (int rr = 0; rr < 2; rr++) {
            const int m = m0 + wm + mi * 16 + rr * 8 + g;
            const int b = m >> 11;
            const int s = m & 2047;
#pragma unroll
            for (int ni = 0; ni < 8; ni++) {
                const int n = n0 + wn + ni * 8 + t * 2;
                const int h = n >> 6;
                const int d = n & 63;
                const size_t off = ((size_t)(b * HH + h) * SS + s) * HD + d;
                float v0 = acc[mi][ni][rr * 2 + 0] + bias[n];
                float v1 = acc[mi][ni][rr * 2 + 1] + bias[n + 1];
                if (which == 0) {
                    float2 v; v.x = v0; v.y = v1;
                    *(float2*)&g_q[off] = v;
                } else if (which == 1) {
                    uint2 hi, lo;
                    hi.x = f2tf32(v0); lo.x = f2tf32(v0 - __uint_as_float(hi.x));
                    hi.y = f2tf32(v1); lo.y = f2tf32(v1 - __uint_as_float(hi.y));
                    *(uint2*)&g_kh[off] = hi;
                    *(uint2*)&g_kl[off] = lo;
                } else {
                    uint2 v; v.x = f2tf32(v0); v.y = f2tf32(v1);
                    *(uint2*)&g_vt[off] = v;
                }
            }
        }
    }
}

// ---------------------------------------------------------------------------
// Kernel 3: output projection. X = g_ctx (tf32 bits). grid = (8, 64), 128 thr.
// ---------------------------------------------------------------------------
__global__ __launch_bounds__(128, 4)
void out_proj_tc(const float* __restrict__ bo, float* __restrict__ out) {
    extern __shared__ uint32_t gsm[];
    float acc[2][8][4];
#pragma unroll
    for (int mi = 0; mi < 2; mi++)
#pragma unroll
        for (int ni = 0; ni < 8; ni++)
#pragma unroll
            for (int r = 0; r < 4; r++) acc[mi][ni][r] = 0.f;

    const int m0 = blockIdx.y * 64;
    const int n0 = blockIdx.x * 128;
    gemm_tile(g_ctx, g_wo, gsm, m0, n0, acc);

    const int tid  = threadIdx.x;
    const int warp = tid >> 5;
    const int lane = tid & 31;
    const int g = lane >> 2, t = lane & 3;
    const int wm = (warp & 1) * 32;
    const int wn = (warp >> 1) * 64;

#pragma unroll
    for (int mi = 0; mi < 2; mi++) {
#pragma unroll
        for (int rr = 0; rr < 2; rr++) {
            const int m = m0 + wm + mi * 16 + rr * 8 + g;
#pragma unroll
            for (int ni = 0; ni < 8; ni++) {
                const int n = n0 + wn + ni * 8 + t * 2;
                float2 v;
                v.x = acc[mi][ni][rr * 2 + 0] + bo[n];
                v.y = acc[mi][ni][rr * 2 + 1] + bo[n + 1];
                *(float2*)&out[(size_t)m * DD + n] = v;
            }
        }
    }
}

// ---------------------------------------------------------------------------
// Kernel 2: tensor-core causal flash attention.
// CTA = 128 q-rows x (head, batch), 8 warps x m16, KV tiles of 64.
// QK^T = qhi*khi + qhi*klo (2 MMAs; dropped qlo*khi term ~2^-12).
// Q-hi frags pinned in registers; Ps aliases the dead Qs region -> only
// 2 barriers per tile.
// ---------------------------------------------------------------------------
#define QP 68
#define FA_QS 0
#define FA_KHI (128 * QP)            // 8704
#define FA_KLO (FA_KHI + 64 * QP)
#define FA_VT  (FA_KLO + 64 * QP)
#define FA_WORDS (FA_VT + 64 * QP)   // 21760 words
#define FA_SMEM (FA_WORDS * 4)       // 87040 B

__global__ __launch_bounds__(256, 2)
void flash_attn_tc() {
    extern __shared__ float smem[];
    float*    Qs  = smem + FA_QS;                 // [128][QP] raw fp32 (dead after split)
    uint32_t* Khi = (uint32_t*)(smem + FA_KHI);   // [64][QP]
    uint32_t* Klo = (uint32_t*)(smem + FA_KLO);   // [64][QP]
    uint32_t* Vt  = (uint32_t*)(smem + FA_VT);    // [64][QP]
    uint32_t* Ps  = (uint32_t*)Qs;                // alias [128][QP]

    const int qt = (gridDim.x - 1) - blockIdx.x;  // heavy tiles first
    const int h  = blockIdx.y;
    const int b  = blockIdx.z;
    const int tid  = threadIdx.x;
    const int warp = tid >> 5;
    const int lane = tid & 31;
    const int g = lane >> 2;
    const int t = lane & 3;
    const int wm = warp * 16;
    const int q0 = qt * 128;

    const float*    __restrict__ Qb = g_q  + (size_t)(b * HH + h) * SS * HD;
    const uint32_t* __restrict__ Hb = g_kh + (size_t)(b * HH + h) * SS * HD;
    const uint32_t* __restrict__ Lb = g_kl + (size_t)(b * HH + h) * SS * HD;
    const uint32_t* __restrict__ Vb = g_vt + (size_t)(b * HH + h) * SS * HD;

    // ldmatrix addressing
    const int sel = lane >> 3;
    const int l7  = lane & 7;
    const int a_row = (sel & 1) * 8 + l7;
    const int a_col = (sel >> 1) * 4;
    const int b_row = (sel >> 1) * 8 + l7;
    const int b_col = (sel & 1) * 4;

    const uint32_t pAddr = (uint32_t)__cvta_generic_to_shared(Ps) +
                           ((wm + a_row) * QP + a_col) * 4;
    uint32_t hAddr[4], lAddr[4];
#pragma unroll
    for (int p = 0; p < 4; p++) {
        hAddr[p] = (uint32_t)__cvta_generic_to_shared(Khi) +
                   ((p * 16 + b_row) * QP + b_col) * 4;
        lAddr[p] = (uint32_t)__cvta_generic_to_shared(Klo) +
                   ((p * 16 + b_row) * QP + b_col) * 4;
    }

    // stage raw Q tile
    {
        const int lr = tid >> 1;
        const int lc = (tid & 1) * 32;
#pragma unroll
        for (int c = 0; c < 8; c++)
            cp_async16(&Qs[lr * QP + lc + c * 4],
                       &Qb[(size_t)(q0 + lr) * HD + lc + c * 4]);
        cp_commit();
        asm volatile("cp.async.wait_group 0;\n");
    }
    __syncthreads();

    // split Q: hi fragments -> registers (lo term dropped)
    uint32_t ahi[8][4];
#pragma unroll
    for (int ks = 0; ks < 8; ks++) {
        const int kb = ks * 8;
        ahi[ks][0] = f2tf32(Qs[(wm + g)     * QP + kb + t]);
        ahi[ks][1] = f2tf32(Qs[(wm + g + 8) * QP + kb + t]);
        ahi[ks][2] = f2tf32(Qs[(wm + g)     * QP + kb + t + 4]);
        ahi[ks][3] = f2tf32(Qs[(wm + g + 8) * QP + kb + t + 4]);
    }
    __syncthreads();   // Qs dead; Ps may now overwrite it

    float oacc[8][4];
#pragma unroll
    for (int ni = 0; ni < 8; ni++)
#pragma unroll
        for (int r = 0; r < 4; r++) oacc[ni][r] = 0.f;
    float m0r = -1e30f, m1r = -1e30f, l0r = 0.f, l1r = 0.f;

    const float scale = 0.125f;
    const int ntiles = 2 * qt + 2;

    const int krow = tid >> 2;                   // 0..63
    const int kc   = (tid & 3) * 16;             // word offset

    for (int tt = 0; tt < ntiles; tt++) {
        const int k0 = tt * 64;
        // load Khi/Klo/Vt tiles (pure copies)
#pragma unroll
        for (int c = 0; c < 4; c++) {
            cp_async16(&Khi[krow * QP + kc + c * 4],
                       &Hb[(size_t)(k0 + krow) * HD + kc + c * 4]);
            cp_async16(&Klo[krow * QP + kc + c * 4],
                       &Lb[(size_t)(k0 + krow) * HD + kc + c * 4]);
            cp_async16(&Vt[krow * QP + kc + c * 4],
                       &Vb[(size_t)(k0 + krow) * HD + kc + c * 4]);
        }
        cp_commit();
        asm volatile("cp.async.wait_group 0;\n");
        __syncthreads();

        // S = Qhi*Khi + Qhi*Klo
        float sacc[8][4];
#pragma unroll
        for (int ni = 0; ni < 8; ni++)
#pragma unroll
            for (int r = 0; r < 4; r++) sacc[ni][r] = 0.f;

#pragma unroll
        for (int ks = 0; ks < 8; ks++) {
            const uint32_t ko = ks * 32;   // bytes
#pragma unroll
            for (int p = 0; p < 4; p++) {
                uint32_t h0, h1, h2, h3, lo0, lo1, lo2, lo3;
                ldsm4(h0, h1, h2, h3, hAddr[p] + ko);
                ldsm4(lo0, lo1, lo2, lo3, lAddr[p] + ko);
                {
                    uint32_t bh[2] = { h0, h1 }, bl[2] = { lo0, lo1 };
                    mma_tf32(sacc[2 * p], ahi[ks], bh);
                    mma_tf32(sacc[2 * p], ahi[ks], bl);
                }
                {
                    uint32_t bh[2] = { h2, h3 }, bl[2] = { lo2, lo3 };
                    mma_tf32(sacc[2 * p + 1], ahi[ks], bh);
                    mma_tf32(sacc[2 * p + 1], ahi[ks], bl);
                }
            }
        }

        // scale + causal mask (only last 2 tiles touch the diagonal)
        const bool need_mask = (tt >= ntiles - 2);
        const int qi0 = q0 + wm + g;
        const int qi1 = qi0 + 8;
#pragma unroll
        for (int ni = 0; ni < 8; ni++) {
            const int c0 = k0 + ni * 8 + 2 * t;
            sacc[ni][0] *= scale; sacc[ni][1] *= scale;
            sacc[ni][2] *= scale; sacc[ni][3] *= scale;
            if (need_mask) {
                if (c0 > qi0)     sacc[ni][0] -= 1e9f;
                if (c0 + 1 > qi0) sacc[ni][1] -= 1e9f;
                if (c0 > qi1)     sacc[ni][2] -= 1e9f;
                if (c0 + 1 > qi1) sacc[ni][3] -= 1e9f;
            }
        }

        // online softmax
        float mx0 = -1e30f, mx1 = -1e30f;
#pragma unroll
        for (int ni = 0; ni < 8; ni++) {
            mx0 = fmaxf(mx0, fmaxf(sacc[ni][0], sacc[ni][1]));
            mx1 = fmaxf(mx1, fmaxf(sacc[ni][2], sacc[ni][3]));
        }
        mx0 = fmaxf(mx0, __shfl_xor_sync(0xffffffffu, mx0, 1));
        mx0 = fmaxf(mx0, __shfl_xor_sync(0xffffffffu, mx0, 2));
        mx1 = fmaxf(mx1, __shfl_xor_sync(0xffffffffu, mx1, 1));
        mx1 = fmaxf(mx1, __shfl_xor_sync(0xffffffffu, mx1, 2));

        const float mn0 = fmaxf(m0r, mx0);
        const float mn1 = fmaxf(m1r, mx1);
        const float al0 = __expf(m0r - mn0);
        const float al1 = __expf(m1r - mn1);
        float s0 = 0.f, s1 = 0.f;
#pragma unroll
        for (int ni = 0; ni < 8; ni++) {
            float p0 = __expf(sacc[ni][0] - mn0);
            float p1 = __expf(sacc[ni][1] - mn0);
            float p2 = __expf(sacc[ni][2] - mn1);
            float p3 = __expf(sacc[ni][3] - mn1);
            s0 += p0 + p1; s1 += p2 + p3;
            uint32_t* pr0 = &Ps[(wm + g)     * QP + ni * 8 + 2 * t];
            uint32_t* pr1 = &Ps[(wm + g + 8) * QP + ni * 8 + 2 * t];
            pr0[0] = f2tf32(p0); pr0[1] = f2tf32(p1);
            pr1[0] = f2tf32(p2); pr1[1] = f2tf32(p3);
        }
        s0 += __shfl_xor_sync(0xffffffffu, s0, 1);
        s0 += __shfl_xor_sync(0xffffffffu, s0, 2);
        s1 += __shfl_xor_sync(0xffffffffu, s1, 1);
        s1 += __shfl_xor_sync(0xffffffffu, s1, 2);
        l0r = l0r * al0 + s0;
        l1r = l1r * al1 + s1;
        m0r = mn0; m1r = mn1;
#pragma unroll
        for (int ni = 0; ni < 8; ni++) {
            oacc[ni][0] *= al0; oacc[ni][1] *= al0;
            oacc[ni][2] *= al1; oacc[ni][3] *= al1;
        }
        __syncwarp();   // Ps rows are per-warp: write->read within warp

        // O += P @ V
#pragma unroll
        for (int ks = 0; ks < 8; ks++) {
            const int kb = ks * 8;
            uint32_t a[4];
            ldsm4(a[0], a[1], a[2], a[3], pAddr + ks * 32);
#pragma unroll
            for (int ni = 0; ni < 8; ni++) {
                uint32_t bf[2];
                bf[0] = Vt[(kb + t)     * QP + ni * 8 + g];
                bf[1] = Vt[(kb + t + 4) * QP + ni * 8 + g];
                mma_tf32(oacc[ni], a, bf);
            }
        }
        __syncthreads();   // Khi/Klo/Vt dead before next tile load
    }

    // normalize + store ctx as tf32 bits in [B,S,D]
    const float inv0 = 1.0f / l0r;
    const float inv1 = 1.0f / l1r;
    const int r0 = q0 + wm + g;
    uint32_t* out0 = g_ctx + ((size_t)(b * SS + r0))     * DD + h * HD;
    uint32_t* out1 = g_ctx + ((size_t)(b * SS + r0 + 8)) * DD + h * HD;
#pragma unroll
    for (int ni = 0; ni < 8; ni++) {
        const int c = ni * 8 + 2 * t;
        uint2 v0, v1;
        v0.x = f2tf32(oacc[ni][0] * inv0); v0.y = f2tf32(oacc[ni][1] * inv0);
        v1.x = f2tf32(oacc[ni][2] * inv1); v1.y = f2tf32(oacc[ni][3] * inv1);
        *(uint2*)&out0[c] = v0;
        *(uint2*)&out1[c] = v1;
    }
}

// ---------------------------------------------------------------------------
extern "C" void kernel_launch(void* const* d_in, const int* in_sizes, int n_in,
                              void* d_out, int out_size) {
    const float* query = (const float*)d_in[0];
    const float* key   = (const float*)d_in[1];
    const float* value = (const float*)d_in[2];
    // d_in[3] = mask (causal; applied analytically in-kernel)
    const float* Wq = (const float*)d_in[4];
    const float* bq = (const float*)d_in[5];
    const float* Wk = (const float*)d_in[6];
    const float* bk = (const float*)d_in[7];
    const float* Wv = (const float*)d_in[8];
    const float* bv = (const float*)d_in[9];
    const float* Wo = (const float*)d_in[10];
    const float* bo = (const float*)d_in[11];
    float* out = (float*)d_out;

    cudaFuncSetAttribute(flash_attn_tc,
                         cudaFuncAttributeMaxDynamicSharedMemorySize, FA_SMEM);
    cudaFuncSetAttribute(qkv_proj_tc,
                         cudaFuncAttributeMaxDynamicSharedMemorySize, PJ_SMEM);
    cudaFuncSetAttribute(out_proj_tc,
                         cudaFuncAttributeMaxDynamicSharedMemorySize, PJ_SMEM);

    dim3 gcvt(1024, 7);
    cvt_tf32_all<<<gcvt, 256>>>(query, key, value, Wq, Wk, Wv, Wo);

    dim3 gproj(DD / 128, MM / 64, 3);
    qkv_proj_tc<<<gproj, 128, PJ_SMEM>>>(bq, bk, bv);

    dim3 gfa(SS / 128, HH, BB);
    flash_attn_tc<<<gfa, 256, FA_SMEM>>>();

    dim3 gout(DD / 128, MM / 64);
    out_proj_tc<<<gout, 128, PJ_SMEM>>>(bo, out);
}